// round 2
// baseline (speedup 1.0000x reference)
#include <cuda_runtime.h>

#define BSZ 2048
#define LSZ 512
#define DSZ 128

// Scratch (no allocations allowed in kernel_launch).
__device__ float g_WT[3][DSZ * DSZ];   // transposed weights: WT[m][e*128+d] = W[m][d*128+e]
__device__ float g_q[BSZ * DSZ];
__device__ float g_k[BSZ * DSZ];
__device__ float g_v[BSZ * DSZ];
__device__ int   g_len[BSZ];           // normalized lengths (dtype auto-detected)

// ---------------------------------------------------------------------------
// Kernel 0a: normalize `lengths` to int32, auto-detecting int32 vs int64
// storage. Viewing the buffer as int32[2048] is always safe. If the data is
// int64 (values in [0,512)), every odd int32 word is a zero high-half; with
// genuine int32 data the odd words are random in [0,512) and the probability
// they are ALL zero is (1/512)^1024 ~ 0.
// ---------------------------------------------------------------------------
__global__ __launch_bounds__(1024) void len_kernel(const int* __restrict__ Lraw) {
    __shared__ int s_any;
    int tid = threadIdx.x;                 // single block, 1024 threads
    if (tid == 0) s_any = 0;
    __syncthreads();
    if (Lraw[2 * tid + 1] != 0) s_any = 1; // benign race, reads idx 1..2047
    __syncthreads();
    if (s_any == 0) {                      // int64 layout
        const long long* L64 = (const long long*)Lraw;
        g_len[2 * tid]     = (int)L64[2 * tid];
        g_len[2 * tid + 1] = (int)L64[2 * tid + 1];
    } else {                               // int32 layout
        g_len[2 * tid]     = Lraw[2 * tid];
        g_len[2 * tid + 1] = Lraw[2 * tid + 1];
    }
}

// ---------------------------------------------------------------------------
// Kernel 0b: transpose the three 128x128 weight matrices into g_WT so the
// projection kernel gets coalesced weight loads (thread d varies fastest).
// ---------------------------------------------------------------------------
__global__ void transpose_kernel(const float* __restrict__ Wq,
                                 const float* __restrict__ Wk,
                                 const float* __restrict__ Wv) {
    int idx = blockIdx.x * blockDim.x + threadIdx.x;   // 0 .. 3*16384-1
    int m = idx >> 14;
    int r = idx & 16383;
    int d = r >> 7;
    int e = r & 127;
    const float* W = (m == 0) ? Wq : ((m == 1) ? Wk : Wv);
    g_WT[m][e * DSZ + d] = W[d * DSZ + e];
}

// ---------------------------------------------------------------------------
// Kernel 1: fused q/k/v projection. 16 batch rows per block, 256 threads.
// q[b,d] = sum_e x[b,e] * W[d,e] + bias[d]  (W accessed via transposed copy).
// ---------------------------------------------------------------------------
__global__ __launch_bounds__(256) void proj_kernel(const float* __restrict__ x,
                                                   const float* __restrict__ bq,
                                                   const float* __restrict__ bk,
                                                   const float* __restrict__ bv) {
    __shared__ float Xs[16][DSZ];
    int tid  = threadIdx.x;
    int row0 = blockIdx.x * 16;

    for (int i = tid; i < 16 * DSZ; i += 256)
        Xs[i >> 7][i & 127] = x[row0 * DSZ + i];
    __syncthreads();

    int d  = tid & 127;
    int rg = tid >> 7;           // 0/1 -> rows rg*8 .. rg*8+7
    const float* Xr = &Xs[rg * 8][0];

    #pragma unroll
    for (int m = 0; m < 3; ++m) {
        const float* WT = g_WT[m];
        float acc[8];
        #pragma unroll
        for (int r = 0; r < 8; ++r) acc[r] = 0.0f;

        for (int e = 0; e < DSZ; ++e) {
            float w = WT[e * DSZ + d];          // coalesced, L1/L2-resident
            #pragma unroll
            for (int r = 0; r < 8; ++r)
                acc[r] += Xr[r * DSZ + e] * w;  // smem broadcast
        }

        const float* bias = (m == 0) ? bq : ((m == 1) ? bk : bv);
        float bb = bias[d];
        float* outp = (m == 0) ? g_q : ((m == 1) ? g_k : g_v);
        #pragma unroll
        for (int r = 0; r < 8; ++r)
            outp[(row0 + rg * 8 + r) * DSZ + d] = acc[r] + bb;
    }
}

// ---------------------------------------------------------------------------
// Kernel 2: attention. One CTA per batch row. Only reads the LIVE suffix
// [512-len, 512) of prev_keys/prev_values (masked prefix is never touched).
// ---------------------------------------------------------------------------
__global__ __launch_bounds__(256) void attn_kernel(const float* __restrict__ K,
                                                   const float* __restrict__ V,
                                                   float* __restrict__ out) {
    __shared__ float sc[LSZ + 1];
    __shared__ float red[8];
    __shared__ float s_inv;
    __shared__ float s_acc[2][DSZ];

    int b    = blockIdx.x;
    int len  = g_len[b];             // 0 .. 511
    int n    = len + 1;              // live entries incl. new pushed one
    int j0   = LSZ - len;            // first live row in prev arrays
    int tid  = threadIdx.x;
    int lane = tid & 31;
    int wid  = tid >> 5;

    const float4 qv = ((const float4*)(g_q + b * DSZ))[lane];
    size_t baseK = (size_t)b * LSZ * DSZ;
    const float inv_sqrt_d = 0.08838834764831845f;   // 1/sqrt(128)

    // ---- Phase 1: scores. Warp w handles live rows i = w, w+8, ...
    for (int i = wid; i < n; i += 8) {
        const float* rp = (i < len) ? (K + baseK + (size_t)(j0 + i) * DSZ)
                                    : (g_k + b * DSZ);
        float4 kv = ((const float4*)rp)[lane];
        float p = kv.x * qv.x + kv.y * qv.y + kv.z * qv.z + kv.w * qv.w;
        p += __shfl_xor_sync(0xffffffffu, p, 16);
        p += __shfl_xor_sync(0xffffffffu, p, 8);
        p += __shfl_xor_sync(0xffffffffu, p, 4);
        p += __shfl_xor_sync(0xffffffffu, p, 2);
        p += __shfl_xor_sync(0xffffffffu, p, 1);
        if (lane == 0) sc[i] = p * inv_sqrt_d;
    }
    __syncthreads();

    // ---- Phase 2a: block max.
    float m = -3.4e38f;
    for (int i = tid; i < n; i += 256) m = fmaxf(m, sc[i]);
    m = fmaxf(m, __shfl_xor_sync(0xffffffffu, m, 16));
    m = fmaxf(m, __shfl_xor_sync(0xffffffffu, m, 8));
    m = fmaxf(m, __shfl_xor_sync(0xffffffffu, m, 4));
    m = fmaxf(m, __shfl_xor_sync(0xffffffffu, m, 2));
    m = fmaxf(m, __shfl_xor_sync(0xffffffffu, m, 1));
    if (lane == 0) red[wid] = m;
    __syncthreads();
    m = red[0];
    #pragma unroll
    for (int w = 1; w < 8; ++w) m = fmaxf(m, red[w]);
    __syncthreads();   // protect red[] before reuse for the sum

    // ---- Phase 2b: exp + block sum (sc overwritten with p = exp(s-m)).
    float lsum = 0.0f;
    for (int i = tid; i < n; i += 256) {
        float p = __expf(sc[i] - m);
        sc[i] = p;
        lsum += p;
    }
    lsum += __shfl_xor_sync(0xffffffffu, lsum, 16);
    lsum += __shfl_xor_sync(0xffffffffu, lsum, 8);
    lsum += __shfl_xor_sync(0xffffffffu, lsum, 4);
    lsum += __shfl_xor_sync(0xffffffffu, lsum, 2);
    lsum += __shfl_xor_sync(0xffffffffu, lsum, 1);
    if (lane == 0) red[wid] = lsum;
    __syncthreads();   // sc (exp'd) and red visible to everyone
    if (tid == 0) {
        float l = 0.0f;
        #pragma unroll
        for (int w = 0; w < 8; ++w) l += red[w];
        s_inv = 1.0f / l;
    }

    // ---- Phase 3: out[d] = (1/l) * sum_i p_i * V_row_i[d].
    // 128-thread group per row; 2 groups interleave rows; 4-way unroll for MLP.
    int d = tid & 127;
    int g = tid >> 7;
    const float* Vb = V + baseK + (size_t)j0 * DSZ + d;

    float a0 = 0.0f, a1 = 0.0f, a2 = 0.0f, a3 = 0.0f;
    int i = g;
    for (; i + 6 < len; i += 8) {
        float p0 = sc[i],     p1 = sc[i + 2];
        float p2 = sc[i + 4], p3 = sc[i + 6];
        a0 += p0 * Vb[(size_t)i * DSZ];
        a1 += p1 * Vb[(size_t)(i + 2) * DSZ];
        a2 += p2 * Vb[(size_t)(i + 4) * DSZ];
        a3 += p3 * Vb[(size_t)(i + 6) * DSZ];
    }
    for (; i < len; i += 2) a0 += sc[i] * Vb[(size_t)i * DSZ];
    if ((len & 1) == g) a0 += sc[len] * g_v[b * DSZ + d];  // new pushed value

    s_acc[g][d] = (a0 + a1) + (a2 + a3);
    __syncthreads();   // also orders s_inv (written by tid 0) before the read below
    if (g == 0)
        out[b * DSZ + d] = (s_acc[0][d] + s_acc[1][d]) * s_inv;
}

// ---------------------------------------------------------------------------
extern "C" void kernel_launch(void* const* d_in, const int* in_sizes, int n_in,
                              void* d_out, int out_size) {
    const float* inputs      = (const float*)d_in[0];
    const float* prev_keys   = (const float*)d_in[1];
    const float* prev_values = (const float*)d_in[2];
    const float* Wq          = (const float*)d_in[3];
    const float* bq          = (const float*)d_in[4];
    const float* Wk          = (const float*)d_in[5];
    const float* bk          = (const float*)d_in[6];
    const float* Wv          = (const float*)d_in[7];
    const float* bv          = (const float*)d_in[8];
    const int*   lengths_raw = (const int*)d_in[9];
    float* out               = (float*)d_out;

    len_kernel<<<1, 1024>>>(lengths_raw);
    transpose_kernel<<<192, 256>>>(Wq, Wk, Wv);
    proj_kernel<<<128, 256>>>(inputs, bq, bk, bv);
    attn_kernel<<<BSZ, 256>>>(prev_keys, prev_values, out);
}

// round 4
// speedup vs baseline: 1.4386x; 1.4386x over previous
#include <cuda_runtime.h>

#define BSZ 2048
#define LSZ 512
#define DSZ 128

__device__ int g_len[BSZ];     // normalized lengths (dtype auto-detected)
__device__ int g_perm[BSZ];    // batch rows sorted by descending length

#define WARP_RED_SUM(p)                                   \
    p += __shfl_xor_sync(0xffffffffu, p, 16);             \
    p += __shfl_xor_sync(0xffffffffu, p, 8);              \
    p += __shfl_xor_sync(0xffffffffu, p, 4);              \
    p += __shfl_xor_sync(0xffffffffu, p, 2);              \
    p += __shfl_xor_sync(0xffffffffu, p, 1);

// ---------------------------------------------------------------------------
// Setup: (a) normalize `lengths` to int32 with int32/int64 auto-detect
// (int64 values < 512 have all-zero odd int32 words; with genuine int32
// random data in [0,512) P(all 1024 odd words zero) = (1/512)^1024 ~ 0),
// (b) counting-sort rows by DESCENDING length into g_perm so the longest
// rows are scheduled first (kills the straggler tail).
// ---------------------------------------------------------------------------
__global__ __launch_bounds__(1024) void setup_kernel(const int* __restrict__ Lraw) {
    __shared__ int cnt[LSZ];
    __shared__ int s_any;
    int tid = threadIdx.x;                  // single block, 1024 threads
    if (tid == 0) s_any = 0;
    for (int i = tid; i < LSZ; i += 1024) cnt[i] = 0;
    __syncthreads();
    if (Lraw[2 * tid + 1] != 0) s_any = 1;  // benign race
    __syncthreads();
    int l0, l1;
    if (s_any == 0) {                       // int64 layout
        const long long* L64 = (const long long*)Lraw;
        l0 = (int)L64[2 * tid];
        l1 = (int)L64[2 * tid + 1];
    } else {                                // int32 layout
        l0 = Lraw[2 * tid];
        l1 = Lraw[2 * tid + 1];
    }
    g_len[2 * tid]     = l0;
    g_len[2 * tid + 1] = l1;
    atomicAdd(&cnt[l0], 1);
    atomicAdd(&cnt[l1], 1);
    __syncthreads();
    if (tid == 0) {                         // exclusive prefix, descending length
        int run = 0;
        for (int l = LSZ - 1; l >= 0; --l) { int c = cnt[l]; cnt[l] = run; run += c; }
    }
    __syncthreads();
    int p0 = atomicAdd(&cnt[l0], 1); g_perm[p0] = 2 * tid;
    int p1 = atomicAdd(&cnt[l1], 1); g_perm[p1] = 2 * tid + 1;
}

// ---------------------------------------------------------------------------
// Fused kernel: per-CTA q/k/v projection + masked softmax attention over the
// LIVE suffix [512-len, 512) only. One CTA per batch row (via g_perm).
// ---------------------------------------------------------------------------
__global__ __launch_bounds__(256) void attn_kernel(
    const float* __restrict__ x,
    const float* __restrict__ K, const float* __restrict__ V,
    const float* __restrict__ Wq, const float* __restrict__ bq,
    const float* __restrict__ Wk, const float* __restrict__ bk,
    const float* __restrict__ Wv, const float* __restrict__ bv,
    float* __restrict__ out)
{
    // NOTE: every array accessed through float4 is explicitly 16B-aligned,
    // and sc is padded to a multiple of 4 floats (513 -> 516) so nothing
    // downstream inherits a 4-byte-offset layout.
    __shared__ __align__(16) float xs[DSZ];
    __shared__ __align__(16) float qs[DSZ];
    __shared__ __align__(16) float ks[DSZ];
    __shared__ __align__(16) float vs[DSZ];
    __shared__ __align__(16) float sc[LSZ + 4];
    __shared__ __align__(16) float s_part[8][DSZ];
    __shared__ float red[8];
    __shared__ float s_inv;

    int tid  = threadIdx.x;
    int lane = tid & 31;
    int wid  = tid >> 5;
    int b    = g_perm[blockIdx.x];
    int len  = g_len[b];                // 0 .. 511
    int n    = len + 1;
    int j0   = LSZ - len;
    const float inv_sqrt_d = 0.08838834764831845f;   // 1/sqrt(128)

    if (tid < 32) ((float4*)xs)[tid] = ((const float4*)(x + (size_t)b * DSZ))[tid];
    __syncthreads();

    // ---- Projection: q[d] = dot(Wq[d,:], x) + bq[d] (same for k,v).
    // Warp w computes rows d = w, w+8, ... of each matrix (W rows coalesced).
    {
        float4 xv = ((const float4*)xs)[lane];
        #pragma unroll
        for (int m = 0; m < 3; ++m) {
            const float* W    = (m == 0) ? Wq : ((m == 1) ? Wk : Wv);
            const float* bias = (m == 0) ? bq : ((m == 1) ? bk : bv);
            float* dst        = (m == 0) ? qs : ((m == 1) ? ks : vs);
            #pragma unroll 4
            for (int j = 0; j < 16; ++j) {
                int d = wid + 8 * j;
                float4 wv = ((const float4*)(W + d * DSZ))[lane];
                float p = fmaf(wv.x, xv.x, fmaf(wv.y, xv.y, fmaf(wv.z, xv.z, wv.w * xv.w)));
                WARP_RED_SUM(p);
                if (lane == 0) dst[d] = p + bias[d];
            }
        }
    }
    __syncthreads();

    // ---- Phase 1: scores over live rows. Warp w: i = w, w+8, ... (x2 unroll)
    size_t base = (size_t)b * LSZ * DSZ;
    const float* Kb = K + base + (size_t)j0 * DSZ;
    {
        float4 qv = ((const float4*)qs)[lane];
        int i = wid;
        for (; i + 8 < len; i += 16) {
            float4 k0 = ((const float4*)(Kb + (size_t)i * DSZ))[lane];
            float4 k1 = ((const float4*)(Kb + (size_t)(i + 8) * DSZ))[lane];
            float p0 = fmaf(k0.x, qv.x, fmaf(k0.y, qv.y, fmaf(k0.z, qv.z, k0.w * qv.w)));
            float p1 = fmaf(k1.x, qv.x, fmaf(k1.y, qv.y, fmaf(k1.z, qv.z, k1.w * qv.w)));
            WARP_RED_SUM(p0);
            WARP_RED_SUM(p1);
            if (lane == 0) { sc[i] = p0 * inv_sqrt_d; sc[i + 8] = p1 * inv_sqrt_d; }
        }
        if (i < len) {
            float4 k0 = ((const float4*)(Kb + (size_t)i * DSZ))[lane];
            float p0 = fmaf(k0.x, qv.x, fmaf(k0.y, qv.y, fmaf(k0.z, qv.z, k0.w * qv.w)));
            WARP_RED_SUM(p0);
            if (lane == 0) sc[i] = p0 * inv_sqrt_d;
        }
        if (wid == (len & 7)) {          // the new pushed entry's score
            float4 kn = ((const float4*)ks)[lane];
            float p = fmaf(kn.x, qv.x, fmaf(kn.y, qv.y, fmaf(kn.z, qv.z, kn.w * qv.w)));
            WARP_RED_SUM(p);
            if (lane == 0) sc[len] = p * inv_sqrt_d;
        }
    }
    __syncthreads();

    // ---- Phase 2a: block max.
    float m = -3.4e38f;
    for (int i = tid; i < n; i += 256) m = fmaxf(m, sc[i]);
    m = fmaxf(m, __shfl_xor_sync(0xffffffffu, m, 16));
    m = fmaxf(m, __shfl_xor_sync(0xffffffffu, m, 8));
    m = fmaxf(m, __shfl_xor_sync(0xffffffffu, m, 4));
    m = fmaxf(m, __shfl_xor_sync(0xffffffffu, m, 2));
    m = fmaxf(m, __shfl_xor_sync(0xffffffffu, m, 1));
    if (lane == 0) red[wid] = m;
    __syncthreads();
    m = red[0];
    #pragma unroll
    for (int w = 1; w < 8; ++w) m = fmaxf(m, red[w]);
    __syncthreads();                     // protect red[] before reuse

    // ---- Phase 2b: exp + block sum.
    float lsum = 0.0f;
    for (int i = tid; i < n; i += 256) {
        float p = __expf(sc[i] - m);
        sc[i] = p;
        lsum += p;
    }
    WARP_RED_SUM(lsum);
    if (lane == 0) red[wid] = lsum;
    __syncthreads();                     // sc (exp'd) and red visible everywhere
    if (tid == 0) {
        float l = 0.0f;
        #pragma unroll
        for (int w = 0; w < 8; ++w) l += red[w];
        s_inv = 1.0f / l;
    }

    // ---- Phase 3: out = (1/l) sum_i p_i V_i. Warp-per-row, float4 accum,
    // no shuffles; warps combined once through smem at the end.
    const float* Vb = V + base + (size_t)j0 * DSZ;
    {
        float4 acc = make_float4(0.f, 0.f, 0.f, 0.f);
        int i = wid;
        for (; i + 8 < len; i += 16) {
            float4 v0 = ((const float4*)(Vb + (size_t)i * DSZ))[lane];
            float4 v1 = ((const float4*)(Vb + (size_t)(i + 8) * DSZ))[lane];
            float p0 = sc[i], p1 = sc[i + 8];
            acc.x = fmaf(p0, v0.x, fmaf(p1, v1.x, acc.x));
            acc.y = fmaf(p0, v0.y, fmaf(p1, v1.y, acc.y));
            acc.z = fmaf(p0, v0.z, fmaf(p1, v1.z, acc.z));
            acc.w = fmaf(p0, v0.w, fmaf(p1, v1.w, acc.w));
        }
        if (i < len) {
            float4 v0 = ((const float4*)(Vb + (size_t)i * DSZ))[lane];
            float p0 = sc[i];
            acc.x = fmaf(p0, v0.x, acc.x);
            acc.y = fmaf(p0, v0.y, acc.y);
            acc.z = fmaf(p0, v0.z, acc.z);
            acc.w = fmaf(p0, v0.w, acc.w);
        }
        if (wid == (len & 7)) {          // the new pushed value
            float4 vn = ((const float4*)vs)[lane];
            float p = sc[len];
            acc.x = fmaf(p, vn.x, acc.x);
            acc.y = fmaf(p, vn.y, acc.y);
            acc.z = fmaf(p, vn.z, acc.z);
            acc.w = fmaf(p, vn.w, acc.w);
        }
        ((float4*)&s_part[wid][0])[lane] = acc;
    }
    __syncthreads();                     // also orders s_inv before read below
    if (tid < DSZ) {
        float s = 0.0f;
        #pragma unroll
        for (int w = 0; w < 8; ++w) s += s_part[w][tid];
        out[(size_t)b * DSZ + tid] = s * s_inv;
    }
}

// ---------------------------------------------------------------------------
extern "C" void kernel_launch(void* const* d_in, const int* in_sizes, int n_in,
                              void* d_out, int out_size) {
    const float* inputs      = (const float*)d_in[0];
    const float* prev_keys   = (const float*)d_in[1];
    const float* prev_values = (const float*)d_in[2];
    const float* Wq          = (const float*)d_in[3];
    const float* bq          = (const float*)d_in[4];
    const float* Wk          = (const float*)d_in[5];
    const float* bk          = (const float*)d_in[6];
    const float* Wv          = (const float*)d_in[7];
    const float* bv          = (const float*)d_in[8];
    const int*   lengths_raw = (const int*)d_in[9];
    float* out               = (float*)d_out;

    setup_kernel<<<1, 1024>>>(lengths_raw);
    attn_kernel<<<BSZ, 256>>>(inputs, prev_keys, prev_values,
                              Wq, bq, Wk, bk, Wv, bv, out);
}

// round 5
// speedup vs baseline: 1.4524x; 1.0096x over previous
#include <cuda_runtime.h>

#define BSZ 2048
#define LSZ 512
#define DSZ 128

__device__ int g_len[BSZ];     // normalized lengths (dtype auto-detected)
__device__ int g_perm[BSZ];    // batch rows sorted by descending length

#define WARP_RED_SUM(p)                                   \
    p += __shfl_xor_sync(0xffffffffu, p, 16);             \
    p += __shfl_xor_sync(0xffffffffu, p, 8);              \
    p += __shfl_xor_sync(0xffffffffu, p, 4);              \
    p += __shfl_xor_sync(0xffffffffu, p, 2);              \
    p += __shfl_xor_sync(0xffffffffu, p, 1);

// Four interleaved reduction trees: each level issues 4 independent SHFLs so
// the chains pipeline at issue rate instead of serializing on SHFL latency.
#define WARP_RED_SUM4(a, b, c, d)                         \
    a += __shfl_xor_sync(0xffffffffu, a, 16);             \
    b += __shfl_xor_sync(0xffffffffu, b, 16);             \
    c += __shfl_xor_sync(0xffffffffu, c, 16);             \
    d += __shfl_xor_sync(0xffffffffu, d, 16);             \
    a += __shfl_xor_sync(0xffffffffu, a, 8);              \
    b += __shfl_xor_sync(0xffffffffu, b, 8);              \
    c += __shfl_xor_sync(0xffffffffu, c, 8);              \
    d += __shfl_xor_sync(0xffffffffu, d, 8);              \
    a += __shfl_xor_sync(0xffffffffu, a, 4);              \
    b += __shfl_xor_sync(0xffffffffu, b, 4);              \
    c += __shfl_xor_sync(0xffffffffu, c, 4);              \
    d += __shfl_xor_sync(0xffffffffu, d, 4);              \
    a += __shfl_xor_sync(0xffffffffu, a, 2);              \
    b += __shfl_xor_sync(0xffffffffu, b, 2);              \
    c += __shfl_xor_sync(0xffffffffu, c, 2);              \
    d += __shfl_xor_sync(0xffffffffu, d, 2);              \
    a += __shfl_xor_sync(0xffffffffu, a, 1);              \
    b += __shfl_xor_sync(0xffffffffu, b, 1);              \
    c += __shfl_xor_sync(0xffffffffu, c, 1);              \
    d += __shfl_xor_sync(0xffffffffu, d, 1);

__device__ __forceinline__ float dot128(float4 a, float4 b) {
    return fmaf(a.x, b.x, fmaf(a.y, b.y, fmaf(a.z, b.z, a.w * b.w)));
}

// ---------------------------------------------------------------------------
// Setup: (a) normalize `lengths` to int32 with int32/int64 auto-detect
// (int64 values < 512 have all-zero odd int32 words; genuine random int32
// data in [0,512) has P(all 1024 odd words zero) = (1/512)^1024 ~ 0),
// (b) counting-sort rows by DESCENDING length into g_perm (longest rows
// scheduled first -> no straggler tail). The prefix scan is a parallel
// shfl-based block scan (the R4 version burned ~8K serial cycles on tid0).
// ---------------------------------------------------------------------------
__global__ __launch_bounds__(1024) void setup_kernel(const int* __restrict__ Lraw) {
    __shared__ int cnt[LSZ];
    __shared__ int wsum[16];
    __shared__ int s_any;
    int tid  = threadIdx.x;                 // single block, 1024 threads
    int lane = tid & 31;
    if (tid == 0) s_any = 0;
    if (tid < LSZ) cnt[tid] = 0;
    __syncthreads();
    if (Lraw[2 * tid + 1] != 0) s_any = 1;  // benign race
    __syncthreads();
    int l0, l1;
    if (s_any == 0) {                       // int64 layout
        const long long* L64 = (const long long*)Lraw;
        l0 = (int)L64[2 * tid];
        l1 = (int)L64[2 * tid + 1];
    } else {                                // int32 layout
        l0 = Lraw[2 * tid];
        l1 = Lraw[2 * tid + 1];
    }
    g_len[2 * tid]     = l0;
    g_len[2 * tid + 1] = l1;
    atomicAdd(&cnt[l0], 1);
    atomicAdd(&cnt[l1], 1);
    __syncthreads();

    // Descending exclusive scan: thread r (r<512) owns length l = 511-r.
    int val = 0, incl = 0;
    if (tid < LSZ) {
        val  = cnt[LSZ - 1 - tid];
        incl = val;
        #pragma unroll
        for (int d = 1; d < 32; d <<= 1) {
            int t = __shfl_up_sync(0xffffffffu, incl, d);
            if (lane >= d) incl += t;
        }
        if (lane == 31) wsum[tid >> 5] = incl;
    }
    __syncthreads();
    if (tid < 16) {
        int w = wsum[tid];
        int wi = w;
        #pragma unroll
        for (int d = 1; d < 16; d <<= 1) {
            int t = __shfl_up_sync(0x0000ffffu, wi, d);
            if (tid >= d) wi += t;
        }
        wsum[tid] = wi - w;                 // exclusive warp offsets
    }
    __syncthreads();
    if (tid < LSZ) cnt[LSZ - 1 - tid] = (incl - val) + wsum[tid >> 5];
    __syncthreads();

    int p0 = atomicAdd(&cnt[l0], 1); g_perm[p0] = 2 * tid;
    int p1 = atomicAdd(&cnt[l1], 1); g_perm[p1] = 2 * tid + 1;
}

// ---------------------------------------------------------------------------
// Fused kernel: per-CTA q/k/v projection + masked softmax attention over the
// LIVE suffix [512-len, 512) only. One CTA per batch row (via g_perm).
// ---------------------------------------------------------------------------
__global__ __launch_bounds__(256) void attn_kernel(
    const float* __restrict__ x,
    const float* __restrict__ K, const float* __restrict__ V,
    const float* __restrict__ Wq, const float* __restrict__ bq,
    const float* __restrict__ Wk, const float* __restrict__ bk,
    const float* __restrict__ Wv, const float* __restrict__ bv,
    float* __restrict__ out)
{
    __shared__ __align__(16) float xs[DSZ];
    __shared__ __align__(16) float qs[DSZ];
    __shared__ __align__(16) float ks[DSZ];
    __shared__ __align__(16) float vs[DSZ];
    __shared__ __align__(16) float sc[LSZ + 4];
    __shared__ __align__(16) float s_part[8][DSZ];
    __shared__ float red[8];
    __shared__ float s_inv;

    int tid  = threadIdx.x;
    int lane = tid & 31;
    int wid  = tid >> 5;
    int b    = g_perm[blockIdx.x];
    int len  = g_len[b];                // 0 .. 511
    int n    = len + 1;
    int j0   = LSZ - len;
    const float inv_sqrt_d = 0.08838834764831845f;   // 1/sqrt(128)

    if (tid < 32) ((float4*)xs)[tid] = ((const float4*)(x + (size_t)b * DSZ))[tid];
    __syncthreads();

    // ---- Projection: q[d] = dot(Wq[d,:], x) + bq[d] (same for k,v).
    // Warp w computes rows d = w, w+8, ...; 4 rows per step, interleaved trees.
    {
        float4 xv = ((const float4*)xs)[lane];
        #pragma unroll
        for (int m = 0; m < 3; ++m) {
            const float* W    = (m == 0) ? Wq : ((m == 1) ? Wk : Wv);
            const float* bias = (m == 0) ? bq : ((m == 1) ? bk : bv);
            float* dst        = (m == 0) ? qs : ((m == 1) ? ks : vs);
            #pragma unroll
            for (int j = 0; j < 4; ++j) {
                int d0 = wid + 32 * j;
                float4 w0 = ((const float4*)(W + (d0     ) * DSZ))[lane];
                float4 w1 = ((const float4*)(W + (d0 +  8) * DSZ))[lane];
                float4 w2 = ((const float4*)(W + (d0 + 16) * DSZ))[lane];
                float4 w3 = ((const float4*)(W + (d0 + 24) * DSZ))[lane];
                float p0 = dot128(w0, xv);
                float p1 = dot128(w1, xv);
                float p2 = dot128(w2, xv);
                float p3 = dot128(w3, xv);
                WARP_RED_SUM4(p0, p1, p2, p3);
                if (lane == 0) {
                    dst[d0]      = p0 + bias[d0];
                    dst[d0 +  8] = p1 + bias[d0 + 8];
                    dst[d0 + 16] = p2 + bias[d0 + 16];
                    dst[d0 + 24] = p3 + bias[d0 + 24];
                }
            }
        }
    }
    __syncthreads();

    // ---- Phase 1: scores over live rows. Warp w: rows w, w+8, ...; 4 rows
    // per iteration (front-batched loads, interleaved reductions). Lane 0
    // tracks the warp-local score max for free (it writes every score).
    size_t base = (size_t)b * LSZ * DSZ;
    const float* Kb = K + base + (size_t)j0 * DSZ;
    float wmax = -3.4e38f;
    {
        float4 qv = ((const float4*)qs)[lane];
        int i = wid;
        for (; i + 24 < len; i += 32) {
            float4 k0 = ((const float4*)(Kb + (size_t)(i     ) * DSZ))[lane];
            float4 k1 = ((const float4*)(Kb + (size_t)(i +  8) * DSZ))[lane];
            float4 k2 = ((const float4*)(Kb + (size_t)(i + 16) * DSZ))[lane];
            float4 k3 = ((const float4*)(Kb + (size_t)(i + 24) * DSZ))[lane];
            float p0 = dot128(k0, qv);
            float p1 = dot128(k1, qv);
            float p2 = dot128(k2, qv);
            float p3 = dot128(k3, qv);
            WARP_RED_SUM4(p0, p1, p2, p3);
            if (lane == 0) {
                p0 *= inv_sqrt_d; p1 *= inv_sqrt_d;
                p2 *= inv_sqrt_d; p3 *= inv_sqrt_d;
                sc[i] = p0; sc[i + 8] = p1; sc[i + 16] = p2; sc[i + 24] = p3;
                wmax = fmaxf(fmaxf(fmaxf(wmax, p0), fmaxf(p1, p2)), p3);
            }
        }
        for (; i < len; i += 8) {
            float4 k0 = ((const float4*)(Kb + (size_t)i * DSZ))[lane];
            float p0 = dot128(k0, qv);
            WARP_RED_SUM(p0);
            if (lane == 0) { p0 *= inv_sqrt_d; sc[i] = p0; wmax = fmaxf(wmax, p0); }
        }
        if (wid == (len & 7)) {          // the new pushed entry's score
            float4 kn = ((const float4*)ks)[lane];
            float p = dot128(kn, qv);
            WARP_RED_SUM(p);
            if (lane == 0) { p *= inv_sqrt_d; sc[len] = p; wmax = fmaxf(wmax, p); }
        }
        if (lane == 0) red[wid] = wmax;
    }
    __syncthreads();

    // ---- Phase 2a: block max from the 8 per-warp maxima.
    float m = red[0];
    #pragma unroll
    for (int w = 1; w < 8; ++w) m = fmaxf(m, red[w]);
    __syncthreads();                     // protect red[] before reuse for sums

    // ---- Phase 2b: exp + block sum (sc overwritten with p = exp(s-m)).
    float lsum = 0.0f;
    for (int i = tid; i < n; i += 256) {
        float p = __expf(sc[i] - m);
        sc[i] = p;
        lsum += p;
    }
    WARP_RED_SUM(lsum);
    if (lane == 0) red[wid] = lsum;
    __syncthreads();                     // sc (exp'd) and red visible everywhere
    if (tid == 0) {
        float l = 0.0f;
        #pragma unroll
        for (int w = 0; w < 8; ++w) l += red[w];
        s_inv = 1.0f / l;
    }

    // ---- Phase 3: out = (1/l) sum_i p_i V_i. Warp-per-row, float4 accum,
    // 4 rows/iter, two independent accumulators; no shuffles.
    const float* Vb = V + base + (size_t)j0 * DSZ;
    {
        float4 acc0 = make_float4(0.f, 0.f, 0.f, 0.f);
        float4 acc1 = make_float4(0.f, 0.f, 0.f, 0.f);
        int i = wid;
        for (; i + 24 < len; i += 32) {
            float4 v0 = ((const float4*)(Vb + (size_t)(i     ) * DSZ))[lane];
            float4 v1 = ((const float4*)(Vb + (size_t)(i +  8) * DSZ))[lane];
            float4 v2 = ((const float4*)(Vb + (size_t)(i + 16) * DSZ))[lane];
            float4 v3 = ((const float4*)(Vb + (size_t)(i + 24) * DSZ))[lane];
            float p0 = sc[i], p1 = sc[i + 8], p2 = sc[i + 16], p3 = sc[i + 24];
            acc0.x = fmaf(p0, v0.x, acc0.x); acc1.x = fmaf(p1, v1.x, acc1.x);
            acc0.y = fmaf(p0, v0.y, acc0.y); acc1.y = fmaf(p1, v1.y, acc1.y);
            acc0.z = fmaf(p0, v0.z, acc0.z); acc1.z = fmaf(p1, v1.z, acc1.z);
            acc0.w = fmaf(p0, v0.w, acc0.w); acc1.w = fmaf(p1, v1.w, acc1.w);
            acc0.x = fmaf(p2, v2.x, acc0.x); acc1.x = fmaf(p3, v3.x, acc1.x);
            acc0.y = fmaf(p2, v2.y, acc0.y); acc1.y = fmaf(p3, v3.y, acc1.y);
            acc0.z = fmaf(p2, v2.z, acc0.z); acc1.z = fmaf(p3, v3.z, acc1.z);
            acc0.w = fmaf(p2, v2.w, acc0.w); acc1.w = fmaf(p3, v3.w, acc1.w);
        }
        for (; i < len; i += 8) {
            float4 v0 = ((const float4*)(Vb + (size_t)i * DSZ))[lane];
            float p0 = sc[i];
            acc0.x = fmaf(p0, v0.x, acc0.x);
            acc0.y = fmaf(p0, v0.y, acc0.y);
            acc0.z = fmaf(p0, v0.z, acc0.z);
            acc0.w = fmaf(p0, v0.w, acc0.w);
        }
        if (wid == (len & 7)) {          // the new pushed value
            float4 vn = ((const float4*)vs)[lane];
            float p = sc[len];
            acc0.x = fmaf(p, vn.x, acc0.x);
            acc0.y = fmaf(p, vn.y, acc0.y);
            acc0.z = fmaf(p, vn.z, acc0.z);
            acc0.w = fmaf(p, vn.w, acc0.w);
        }
        acc0.x += acc1.x; acc0.y += acc1.y; acc0.z += acc1.z; acc0.w += acc1.w;
        ((float4*)&s_part[wid][0])[lane] = acc0;
    }
    __syncthreads();                     // also orders s_inv before read below
    if (tid < DSZ) {
        float s = 0.0f;
        #pragma unroll
        for (int w = 0; w < 8; ++w) s += s_part[w][tid];
        out[(size_t)b * DSZ + tid] = s * s_inv;
    }
}

// ---------------------------------------------------------------------------
extern "C" void kernel_launch(void* const* d_in, const int* in_sizes, int n_in,
                              void* d_out, int out_size) {
    const float* inputs      = (const float*)d_in[0];
    const float* prev_keys   = (const float*)d_in[1];
    const float* prev_values = (const float*)d_in[2];
    const float* Wq          = (const float*)d_in[3];
    const float* bq          = (const float*)d_in[4];
    const float* Wk          = (const float*)d_in[5];
    const float* bk          = (const float*)d_in[6];
    const float* Wv          = (const float*)d_in[7];
    const float* bv          = (const float*)d_in[8];
    const int*   lengths_raw = (const int*)d_in[9];
    float* out               = (float*)d_out;

    setup_kernel<<<1, 1024>>>(lengths_raw);
    attn_kernel<<<BSZ, 256>>>(inputs, prev_keys, prev_values,
                              Wq, bq, Wk, bk, Wv, bv, out);
}